// round 16
// baseline (speedup 1.0000x reference)
#include <cuda_runtime.h>
#include <cuda_bf16.h>
#include <cstdint>

#define NB 32
#define NM 2048
#define ND 1024
#define NK 64
#define BM (NB*NM)   // 65536 rows total

// ---------------- scratch (device globals; no allocs allowed) ----------------
__device__ int8_t        g_x8[(size_t)BM * ND];        // 64 MB: q = sat8(round(16*x))
__device__ __nv_bfloat16 g_w16[NK * ND];               // W in bf16, k-PERMUTED within 16-groups
__device__ __nv_bfloat16 g_a[(size_t)BM * NK];         // p[m,k] * inv_m  (bf16)
__device__ float         g_asum[NB * NK];              // sum_m p[b,m,k]  (unscaled)
__device__ float         g_vraw[(size_t)2 * NB * NK * ND]; // 2 M-split partials of A'^T X

// ---------------- helpers ----------------
static __device__ __forceinline__ unsigned s2u(const void* p) {
    return (unsigned)__cvta_generic_to_shared(p);
}
static __device__ __forceinline__ void cp16(unsigned dst, const void* src) {
    asm volatile("cp.async.cg.shared.global [%0], [%1], 16;\n" :: "r"(dst), "l"(src));
}
static __device__ __forceinline__ void cp_commit() {
    asm volatile("cp.async.commit_group;\n");
}
template<int N> static __device__ __forceinline__ void cp_wait() {
    asm volatile("cp.async.wait_group %0;\n" :: "n"(N));
}
static __device__ __forceinline__ void ldsm_x4(unsigned& r0, unsigned& r1, unsigned& r2, unsigned& r3, unsigned a) {
    asm volatile("ldmatrix.sync.aligned.m8n8.x4.shared.b16 {%0,%1,%2,%3}, [%4];"
                 : "=r"(r0), "=r"(r1), "=r"(r2), "=r"(r3) : "r"(a));
}
static __device__ __forceinline__ void ldsm_x4t(unsigned& r0, unsigned& r1, unsigned& r2, unsigned& r3, unsigned a) {
    asm volatile("ldmatrix.sync.aligned.m8n8.x4.trans.shared.b16 {%0,%1,%2,%3}, [%4];"
                 : "=r"(r0), "=r"(r1), "=r"(r2), "=r"(r3) : "r"(a));
}
static __device__ __forceinline__ void mma16816(float* c,
        unsigned a0, unsigned a1, unsigned a2, unsigned a3, unsigned b0, unsigned b1) {
    asm volatile("mma.sync.aligned.m16n8k16.row.col.f32.bf16.bf16.f32 "
                 "{%0,%1,%2,%3}, {%4,%5,%6,%7}, {%8,%9}, {%0,%1,%2,%3};"
                 : "+f"(c[0]), "+f"(c[1]), "+f"(c[2]), "+f"(c[3])
                 : "r"(a0), "r"(a1), "r"(a2), "r"(a3), "r"(b0), "r"(b1));
}
static __device__ __forceinline__ unsigned packbf(float a, float b) {
    __nv_bfloat162 h;
    h.x = __float2bfloat16_rn(a);
    h.y = __float2bfloat16_rn(b);
    return *reinterpret_cast<unsigned*>(&h);
}
// pack 4 floats -> 4 saturated int8 (x16 scale), memory order a,b,c,d
static __device__ __forceinline__ unsigned pack_s8(float a, float b, float c, float d) {
    int ia = __float2int_rn(a * 16.f), ib = __float2int_rn(b * 16.f);
    int ic = __float2int_rn(c * 16.f), id = __float2int_rn(d * 16.f);
    unsigned hi, r;
    asm("cvt.pack.sat.s8.s32.b32 %0, %1, %2, 0;"  : "=r"(hi) : "r"(id), "r"(ic));
    asm("cvt.pack.sat.s8.s32.b32 %0, %1, %2, %3;" : "=r"(r)  : "r"(ib), "r"(ia), "r"(hi));
    return r;
}
// 4 int8 (one u32) -> 2 bf16x2 words (exact: |q| <= 127)
static __device__ __forceinline__ void cvt8(unsigned u, unsigned& lo, unsigned& hi) {
    float f0 = (float)(int)(int8_t)(u);
    float f1 = (float)(int)(int8_t)(u >> 8);
    float f2 = (float)(int)(int8_t)(u >> 16);
    float f3 = (float)(int)(int8_t)(u >> 24);
    lo = packbf(f0, f1);
    hi = packbf(f2, f3);
}

// ---------------- kernel 0: W -> bf16 (k-permuted), zero a_sum ----------------
__global__ __launch_bounds__(256) void k_wconv(const float* __restrict__ W) {
    int i = blockIdx.x * 256 + threadIdx.x;       // grid 256 -> exactly NK*ND
    int kl = i & (ND - 1);
    int j  = kl & 15;
    int sl = 2 * (j >> 2) + (j & 1) + ((j & 2) ? 8 : 0);
    int oc = (kl & ~15) | sl;
    g_w16[(i & ~(ND - 1)) | oc] = __float2bfloat16_rn(W[i]);
    if (i < NB * NK) g_asum[i] = 0.f;
    asm volatile("griddepcontrol.launch_dependents;");
}

// ============ fused: x->int8 + logits GEMM + row-norm + softmax + a_sum ============
// (R14-proven skeleton; only the x-store path changes to int8.) 128 rows/block.
#define NL_SMEM 52992
__global__ __launch_bounds__(256, 2) void k_nl(const float* __restrict__ x) {
    extern __shared__ __align__(16) unsigned char dsm[];
    __nv_bfloat16* wt[2] = { (__nv_bfloat16*)dsm, (__nv_bfloat16*)(dsm + 9216) };
    float* lg    = (float*)(dsm + 18432);
    float* ssrow = (float*)(dsm + 52224);
    float* sas   = (float*)(dsm + 52736);

    const int tid = threadIdx.x, lane = tid & 31, warp = tid >> 5;
    const int m0 = blockIdx.x * 128;
    const int b  = m0 >> 11;

    if (tid < 64) sas[tid] = 0.f;

    const int gr = lane >> 2, q = lane & 3;
    const int ar = warp * 16;
    const size_t row0 = (size_t)(m0 + ar + gr);     // lo row; hi row = row0 + 8

    float4 xr[2][4][2];
    float ss0 = 0.f, ss1 = 0.f;

    float acc[8][4];
#pragma unroll
    for (int i = 0; i < 8; i++)
#pragma unroll
        for (int j = 0; j < 4; j++) acc[i][j] = 0.f;

    auto ldw = [&](int ch, int s) {
#pragma unroll
        for (int it = 0; it < 2; it++) {
            int idx = tid + it * 256;
            int r = idx >> 3, c = idx & 7;
            cp16(s2u(wt[s] + r * 72 + c * 8), g_w16 + (size_t)r * ND + ch * 64 + c * 8);
        }
        cp_commit();
    };

    const float* xb = x + row0 * ND + q * 4;

    // ---- prologue: x first (independent of W), then PDL-wait, then W ----
#pragma unroll
    for (int ds = 0; ds < 4; ds++) {
        xr[0][ds][0] = *(const float4*)(xb + ds * 16);
        xr[0][ds][1] = *(const float4*)(xb + ds * 16 + 8 * ND);
    }
#pragma unroll
    for (int ds = 0; ds < 4; ds++) {
        xr[1][ds][0] = *(const float4*)(xb + 64 + ds * 16);
        xr[1][ds][1] = *(const float4*)(xb + 64 + ds * 16 + 8 * ND);
    }
    asm volatile("griddepcontrol.wait;" ::: "memory");   // g_w16 ready past here
    ldw(0, 0);
    ldw(1, 1);
    cp_wait<1>();
    __syncthreads();

    auto body = [&](int ch, int cb) {
#pragma unroll
        for (int ds = 0; ds < 4; ds++) {
            float4 f0 = xr[cb][ds][0];
            float4 f1 = xr[cb][ds][1];
            ss0 += f0.x * f0.x + f0.y * f0.y + f0.z * f0.z + f0.w * f0.w;
            ss1 += f1.x * f1.x + f1.y * f1.y + f1.z * f1.z + f1.w * f1.w;
            unsigned a0 = packbf(f0.x, f0.y), a2 = packbf(f0.z, f0.w);
            unsigned a1 = packbf(f1.x, f1.y), a3 = packbf(f1.z, f1.w);
            {   // int8 out (q = sat8(16x)) for k_vlad
                int8_t* gx = g_x8 + row0 * ND + ch * 64 + ds * 16 + q * 4;
                *(unsigned*)gx            = pack_s8(f0.x, f0.y, f0.z, f0.w);
                *(unsigned*)(gx + 8 * ND) = pack_s8(f1.x, f1.y, f1.z, f1.w);
            }
#pragma unroll
            for (int nt = 0; nt < 8; nt += 2) {
                unsigned b0, b1, b2, b3;
                int r = nt * 8 + (lane & 7) + ((lane >> 4) & 1) * 8;
                int c = ds * 16 + ((lane >> 3) & 1) * 8;
                ldsm_x4(b0, b1, b2, b3, s2u(wt[cb] + r * 72 + c));
                mma16816(acc[nt],     a0, a1, a2, a3, b0, b1);
                mma16816(acc[nt + 1], a0, a1, a2, a3, b2, b3);
            }
        }
        if (ch + 2 < 16) {
#pragma unroll
            for (int ds = 0; ds < 4; ds++) {
                xr[cb][ds][0] = *(const float4*)(xb + (ch + 2) * 64 + ds * 16);
                xr[cb][ds][1] = *(const float4*)(xb + (ch + 2) * 64 + ds * 16 + 8 * ND);
            }
        }
        __syncthreads();                 // all reads of wt[cb] complete
        if (ch + 2 < 16) { ldw(ch + 2, cb); cp_wait<1>(); }
        else             cp_wait<0>();
        __syncthreads();                 // wt writes visible
    };
    for (int ch2 = 0; ch2 < 16; ch2 += 2) {
        body(ch2,     0);
        body(ch2 + 1, 1);
    }

    // ---- row sum-of-squares: reduce over the 4 q-lanes ----
    ss0 += __shfl_xor_sync(0xffffffffu, ss0, 1);
    ss0 += __shfl_xor_sync(0xffffffffu, ss0, 2);
    ss1 += __shfl_xor_sync(0xffffffffu, ss1, 1);
    ss1 += __shfl_xor_sync(0xffffffffu, ss1, 2);
    if (q == 0) {
        ssrow[ar + gr]     = ss0;
        ssrow[ar + gr + 8] = ss1;
    }
    // ---- dump logits ----
#pragma unroll
    for (int nt = 0; nt < 8; nt++) {
        int r0 = ar + (lane >> 2);
        int c0 = nt * 8 + 2 * (lane & 3);
        lg[r0 * 66 + c0]           = acc[nt][0];
        lg[r0 * 66 + c0 + 1]       = acc[nt][1];
        lg[(r0 + 8) * 66 + c0]     = acc[nt][2];
        lg[(r0 + 8) * 66 + c0 + 1] = acc[nt][3];
    }
    __syncthreads();

    // ---- softmax: each warp does its 16 rows; lane owns cols (2l, 2l+1) ----
    float s0 = 0.f, s1 = 0.f;
    const int c0 = 2 * lane, c1 = 2 * lane + 1;
#pragma unroll 1
    for (int r = 0; r < 16; r++) {
        int rr = ar + r;
        float inv = 1.0f / fmaxf(sqrtf(ssrow[rr]), 1e-12f);
        float v0 = lg[rr * 66 + c0] * inv, v1 = lg[rr * 66 + c1] * inv;
        float mx = fmaxf(v0, v1);
#pragma unroll
        for (int o = 16; o > 0; o >>= 1) mx = fmaxf(mx, __shfl_xor_sync(0xffffffffu, mx, o));
        float e0 = expf(v0 - mx), e1 = expf(v1 - mx);
        float sm = e0 + e1;
#pragma unroll
        for (int o = 16; o > 0; o >>= 1) sm += __shfl_xor_sync(0xffffffffu, sm, o);
        float is = 1.0f / sm;
        float p0 = e0 * is, p1 = e1 * is;
        s0 += p0; s1 += p1;
        __nv_bfloat162 h;                    // store p * inv_m  (normalization folded in)
        h.x = __float2bfloat16_rn(p0 * inv);
        h.y = __float2bfloat16_rn(p1 * inv);
        ((__nv_bfloat162*)(g_a + (size_t)(m0 + rr) * NK))[lane] = h;
    }
    atomicAdd(&sas[c0], s0);
    atomicAdd(&sas[c1], s1);
    __syncthreads();
    if (tid < 64) atomicAdd(&g_asum[b * NK + tid], sas[tid]);
    asm volatile("griddepcontrol.launch_dependents;");
}

// ============ kernel: vlad partial[z][b] = A'(b, z-half)^T @ X(b, z-half) ============
// grid (8 d-tiles, 32 b, 2 m-splits). x now int8: LDG.128 regs -> exact int8->bf16
// dequant -> STS into the bf16 tile (register double-buffered, mirroring k_nl's x
// pipeline). a-tiles stay cp.async double-buffered. Epilogue scales by 1/16.
// dyn smem: at[2] 9216 ea @0 | xt[2] bf16 17408 ea @18432 -> 53248 B
#define VL_SMEM 53248
__global__ __launch_bounds__(256) void k_vlad() {
    extern __shared__ __align__(16) unsigned char dsm[];
    __nv_bfloat16* at[2] = { (__nv_bfloat16*)dsm,           (__nv_bfloat16*)(dsm + 9216) };
    __nv_bfloat16* xt[2] = { (__nv_bfloat16*)(dsm + 18432), (__nv_bfloat16*)(dsm + 35840) };

    const int tid = threadIdx.x, lane = tid & 31, warp = tid >> 5;
    const int b  = blockIdx.y;
    const int z  = blockIdx.z;
    const int d0 = blockIdx.x * 128;
    const int wk = (warp & 3) * 16;     // k-row base for this warp
    const int wd = (warp >> 2) * 64;    // d-col base within tile

    const size_t rowbase = (size_t)b * NM + (size_t)z * (NM / 2);

    // x loader mapping: thread owns tile row xrr = tid>>2, 32-byte quarter q4
    const int xrr = tid >> 2, q4 = tid & 3;

    float acc[8][4];
#pragma unroll
    for (int i = 0; i < 8; i++)
#pragma unroll
        for (int j = 0; j < 4; j++) acc[i][j] = 0.f;

    uint4 qv[2][2];
    auto ldgq = [&](int mc, int cb) {
        const int8_t* p = g_x8 + (rowbase + mc * 64 + xrr) * ND + d0 + q4 * 32;
        qv[cb][0] = *(const uint4*)p;
        qv[cb][1] = *(const uint4*)(p + 16);
    };
    auto cvts = [&](int cb, int s) {
        unsigned char* base = (unsigned char*)xt[s] + (size_t)xrr * 272 + q4 * 64;
#pragma unroll
        for (int h = 0; h < 2; h++) {
            unsigned w0 = (h ? qv[cb][1].x : qv[cb][0].x);
            unsigned w1 = (h ? qv[cb][1].y : qv[cb][0].y);
            unsigned w2 = (h ? qv[cb][1].z : qv[cb][0].z);
            unsigned w3 = (h ? qv[cb][1].w : qv[cb][0].w);
            unsigned o0, o1, o2, o3, o4, o5, o6, o7;
            cvt8(w0, o0, o1);
            cvt8(w1, o2, o3);
            cvt8(w2, o4, o5);
            cvt8(w3, o6, o7);
            uint4* dst = (uint4*)(base + h * 32);
            dst[0] = make_uint4(o0, o1, o2, o3);
            dst[1] = make_uint4(o4, o5, o6, o7);
        }
    };
    auto cpa = [&](int mc, int s) {
        const size_t mrow = rowbase + mc * 64;
#pragma unroll
        for (int it = 0; it < 2; it++) {     // a tile: 64 m x 64 k
            int idx = tid + it * 256;
            int r = idx >> 3, c = idx & 7;
            cp16(s2u(at[s] + r * 72 + c * 8), g_a + (mrow + r) * NK + c * 8);
        }
        cp_commit();
    };

    asm volatile("griddepcontrol.wait;" ::: "memory");   // k_nl outputs ready past here

    ldgq(0, 0);
    cpa(0, 0);
    for (int mc = 0; mc < 16; mc++) {
        const int s = mc & 1;
        cvts(s, s);                                // dequant chunk mc into xt[s]
        if (mc + 1 < 16) { ldgq(mc + 1, s ^ 1); cpa(mc + 1, s ^ 1); cp_wait<1>(); }
        else             cp_wait<0>();
        __syncthreads();                           // at[s] + xt[s] ready
#pragma unroll
        for (int ms = 0; ms < 4; ms++) {
            int mb = ms * 16;
            unsigned a0, a1, a2, a3;
            {   // A = a^T (k x m) from [m][k] storage -> ldmatrix.trans
                int i = lane & 7;
                int r = mb + i + ((lane >> 4) & 1) * 8;
                int c = wk + ((lane >> 3) & 1) * 8;
                ldsm_x4t(a0, a1, a2, a3, s2u(at[s] + r * 72 + c));
            }
#pragma unroll
            for (int nt = 0; nt < 8; nt += 2) {
                unsigned b0, b1, b2, b3;
                int r = mb + (lane & 7) + ((lane >> 3) & 1) * 8;
                int c = wd + nt * 8 + ((lane >> 4) & 1) * 8;
                ldsm_x4t(b0, b1, b2, b3, s2u(xt[s] + r * 136 + c));
                mma16816(acc[nt],     a0, a1, a2, a3, b0, b1);
                mma16816(acc[nt + 1], a0, a1, a2, a3, b2, b3);
            }
        }
        __syncthreads();                           // reads done before next overwrite
    }

    float* vb = g_vraw + ((size_t)z * NB + b) * NK * ND;
#pragma unroll
    for (int nt = 0; nt < 8; nt++) {
        int k0 = wk + (lane >> 2);
        int dd = d0 + wd + nt * 8 + 2 * (lane & 3);
        *(float2*)(vb + (size_t)k0 * ND + dd) =
            make_float2(acc[nt][0] * 0.0625f, acc[nt][1] * 0.0625f);
        *(float2*)(vb + (size_t)(k0 + 8) * ND + dd) =
            make_float2(acc[nt][2] * 0.0625f, acc[nt][3] * 0.0625f);
    }
    asm volatile("griddepcontrol.launch_dependents;");
}

// ---------------- kernel: centroid subtract + intra-norm + global(1/8) ----------------
__global__ __launch_bounds__(256) void k_final(const float* __restrict__ cent,
                                               float* __restrict__ out) {
    const int bk = blockIdx.x;           // b*64 + k
    const int k  = bk & 63;
    const int tid = threadIdx.x, lane = tid & 31, warp = tid >> 5;
    asm volatile("griddepcontrol.wait;" ::: "memory");   // k_vlad outputs ready
    const float* vr0 = g_vraw + (size_t)bk * ND;
    const float* vr1 = g_vraw + (size_t)NB * NK * ND + (size_t)bk * ND;
    const float* cp = cent + (size_t)k * ND;
    const float as = g_asum[bk];
    float v[4];
    float ss = 0.f;
#pragma unroll
    for (int i = 0; i < 4; i++) {
        int d = tid + i * 256;
        v[i] = vr0[d] + vr1[d] - as * cp[d];
        ss += v[i] * v[i];
    }
#pragma unroll
    for (int o = 16; o > 0; o >>= 1) ss += __shfl_xor_sync(0xffffffffu, ss, o);
    __shared__ float red[8];
    if (lane == 0) red[warp] = ss;
    __syncthreads();
    float tot = red[0] + red[1] + red[2] + red[3] + red[4] + red[5] + red[6] + red[7];
    // intra-normalize; global norm is exactly sqrt(64)=8 after intra-normalization
    float inv = 0.125f / fmaxf(sqrtf(tot), 1e-12f);
    float* op = out + (size_t)bk * ND;
#pragma unroll
    for (int i = 0; i < 4; i++) op[tid + i * 256] = v[i] * inv;
}

// ---------------- launch (R14 PDL chain) ----------------
extern "C" void kernel_launch(void* const* d_in, const int* in_sizes, int n_in,
                              void* d_out, int out_size) {
    const float* x    = (const float*)d_in[0];
    const float* W    = (const float*)d_in[1];
    const float* cent = (const float*)d_in[2];
    float* out = (float*)d_out;

    static int configured = 0;
    if (!configured) {
        cudaFuncSetAttribute(k_nl,   cudaFuncAttributeMaxDynamicSharedMemorySize, NL_SMEM);
        cudaFuncSetAttribute(k_vlad, cudaFuncAttributeMaxDynamicSharedMemorySize, VL_SMEM);
        configured = 1;
    }

    k_wconv<<<256, 256>>>(W);

    cudaLaunchAttribute pdl[1];
    pdl[0].id = cudaLaunchAttributeProgrammaticStreamSerialization;
    pdl[0].val.programmaticStreamSerializationAllowed = 1;

    {
        cudaLaunchConfig_t cfg{};
        cfg.gridDim = dim3(512, 1, 1);
        cfg.blockDim = dim3(256, 1, 1);
        cfg.dynamicSmemBytes = NL_SMEM;
        cfg.stream = 0;
        cfg.attrs = pdl;
        cfg.numAttrs = 1;
        cudaLaunchKernelEx(&cfg, k_nl, x);
    }
    {
        cudaLaunchConfig_t cfg{};
        cfg.gridDim = dim3(8, 32, 2);
        cfg.blockDim = dim3(256, 1, 1);
        cfg.dynamicSmemBytes = VL_SMEM;
        cfg.stream = 0;
        cfg.attrs = pdl;
        cfg.numAttrs = 1;
        cudaLaunchKernelEx(&cfg, k_vlad);
    }
    {
        cudaLaunchConfig_t cfg{};
        cfg.gridDim = dim3(2048, 1, 1);
        cfg.blockDim = dim3(256, 1, 1);
        cfg.dynamicSmemBytes = 0;
        cfg.stream = 0;
        cfg.attrs = pdl;
        cfg.numAttrs = 1;
        cudaLaunchKernelEx(&cfg, k_final, cent, out);
    }
}

// round 17
// speedup vs baseline: 1.1211x; 1.1211x over previous
#include <cuda_runtime.h>
#include <cuda_bf16.h>
#include <cstdint>

#define NB 32
#define NM 2048
#define ND 1024
#define NK 64
#define BM (NB*NM)   // 65536 rows total

// ---------------- scratch (device globals; no allocs allowed) ----------------
__device__ __nv_bfloat16 g_x16[(size_t)BM * ND];       // 128 MB bf16(x) RAW (not normalized)
__device__ __nv_bfloat16 g_w16[NK * ND];               // W in bf16, k-PERMUTED within 16-groups
__device__ __nv_bfloat16 g_a[(size_t)BM * NK];         // p[m,k] * inv_m  (bf16)
__device__ float         g_asum[NB * NK];              // sum_m p[b,m,k]  (unscaled)
__device__ float         g_ssq[NB * NK * 8];           // per-(b,k) sumsq partials, 8 d-tiles
__device__ int           g_cnt[NB];                    // arrival counters (one per b)

// ---------------- helpers ----------------
static __device__ __forceinline__ unsigned s2u(const void* p) {
    return (unsigned)__cvta_generic_to_shared(p);
}
static __device__ __forceinline__ void cp16(unsigned dst, const void* src) {
    asm volatile("cp.async.cg.shared.global [%0], [%1], 16;\n" :: "r"(dst), "l"(src));
}
static __device__ __forceinline__ void cp_commit() {
    asm volatile("cp.async.commit_group;\n");
}
template<int N> static __device__ __forceinline__ void cp_wait() {
    asm volatile("cp.async.wait_group %0;\n" :: "n"(N));
}
static __device__ __forceinline__ void ldsm_x4(unsigned& r0, unsigned& r1, unsigned& r2, unsigned& r3, unsigned a) {
    asm volatile("ldmatrix.sync.aligned.m8n8.x4.shared.b16 {%0,%1,%2,%3}, [%4];"
                 : "=r"(r0), "=r"(r1), "=r"(r2), "=r"(r3) : "r"(a));
}
static __device__ __forceinline__ void ldsm_x4t(unsigned& r0, unsigned& r1, unsigned& r2, unsigned& r3, unsigned a) {
    asm volatile("ldmatrix.sync.aligned.m8n8.x4.trans.shared.b16 {%0,%1,%2,%3}, [%4];"
                 : "=r"(r0), "=r"(r1), "=r"(r2), "=r"(r3) : "r"(a));
}
static __device__ __forceinline__ void mma16816(float* c,
        unsigned a0, unsigned a1, unsigned a2, unsigned a3, unsigned b0, unsigned b1) {
    asm volatile("mma.sync.aligned.m16n8k16.row.col.f32.bf16.bf16.f32 "
                 "{%0,%1,%2,%3}, {%4,%5,%6,%7}, {%8,%9}, {%0,%1,%2,%3};"
                 : "+f"(c[0]), "+f"(c[1]), "+f"(c[2]), "+f"(c[3])
                 : "r"(a0), "r"(a1), "r"(a2), "r"(a3), "r"(b0), "r"(b1));
}
static __device__ __forceinline__ unsigned packbf(float a, float b) {
    __nv_bfloat162 h;
    h.x = __float2bfloat16_rn(a);
    h.y = __float2bfloat16_rn(b);
    return *reinterpret_cast<unsigned*>(&h);
}

// ---------------- kernel 0: W -> bf16 (k-permuted), zero a_sum + counters ----------------
// Permutation within each 16-col group: logical j -> slot 2*(j>>2)+(j&1)+((j&2)?8:0),
// matching A-fragments built straight from float4 LDGs. Fires PDL trigger.
__global__ __launch_bounds__(256) void k_wconv(const float* __restrict__ W) {
    int i = blockIdx.x * 256 + threadIdx.x;       // grid 256 -> exactly NK*ND
    int kl = i & (ND - 1);
    int j  = kl & 15;
    int sl = 2 * (j >> 2) + (j & 1) + ((j & 2) ? 8 : 0);
    int oc = (kl & ~15) | sl;
    g_w16[(i & ~(ND - 1)) | oc] = __float2bfloat16_rn(W[i]);
    if (i < NB * NK) g_asum[i] = 0.f;
    if (i < NB) g_cnt[i] = 0;
    asm volatile("griddepcontrol.launch_dependents;");
}

// ============ fused: x->bf16 + logits GEMM + row-norm + softmax + a_sum ============
// (R14-proven body, byte-identical.) 128 rows per block (grid 512). A-operand
// fragments built directly from x LDG.128 registers; raw bf16 streamed to g_x16.
// W tiles double-buffered via cp.async, consumed with ldsm_x4. PDL: x prologue
// issues before k_wconv finishes; griddepcontrol.wait guards g_w16; trigger
// fired at the END (late — early trigger regressed in R15).
//
// dyn smem layout (bytes):
//   wt[2] [64][72] bf16 @ 0      18432
//   lg    [128][66] f32 @ 18432  33792
//   ssrow [128]     f32 @ 52224    512
//   sas   [64]      f32 @ 52736    256
#define NL_SMEM 52992
__global__ __launch_bounds__(256, 2) void k_nl(const float* __restrict__ x) {
    extern __shared__ __align__(16) unsigned char dsm[];
    __nv_bfloat16* wt[2] = { (__nv_bfloat16*)dsm, (__nv_bfloat16*)(dsm + 9216) };
    float* lg    = (float*)(dsm + 18432);
    float* ssrow = (float*)(dsm + 52224);
    float* sas   = (float*)(dsm + 52736);

    const int tid = threadIdx.x, lane = tid & 31, warp = tid >> 5;
    const int m0 = blockIdx.x * 128;
    const int b  = m0 >> 11;

    if (tid < 64) sas[tid] = 0.f;

    const int gr = lane >> 2, q = lane & 3;
    const int ar = warp * 16;                       // warp's 16 m-rows
    const size_t row0 = (size_t)(m0 + ar + gr);     // lo row; hi row = row0 + 8

    float4 xr[2][4][2];
    float ss0 = 0.f, ss1 = 0.f;

    float acc[8][4];
#pragma unroll
    for (int i = 0; i < 8; i++)
#pragma unroll
        for (int j = 0; j < 4; j++) acc[i][j] = 0.f;

    auto ldw = [&](int ch, int s) {
#pragma unroll
        for (int it = 0; it < 2; it++) {
            int idx = tid + it * 256;
            int r = idx >> 3, c = idx & 7;
            cp16(s2u(wt[s] + r * 72 + c * 8), g_w16 + (size_t)r * ND + ch * 64 + c * 8);
        }
        cp_commit();
    };

    const float* xb = x + row0 * ND + q * 4;

    // ---- prologue: x first (independent of W), then PDL-wait, then W ----
#pragma unroll
    for (int ds = 0; ds < 4; ds++) {
        xr[0][ds][0] = *(const float4*)(xb + ds * 16);
        xr[0][ds][1] = *(const float4*)(xb + ds * 16 + 8 * ND);
    }
#pragma unroll
    for (int ds = 0; ds < 4; ds++) {
        xr[1][ds][0] = *(const float4*)(xb + 64 + ds * 16);
        xr[1][ds][1] = *(const float4*)(xb + 64 + ds * 16 + 8 * ND);
    }
    asm volatile("griddepcontrol.wait;" ::: "memory");   // g_w16 + zeroed cnt ready
    ldw(0, 0);
    ldw(1, 1);
    cp_wait<1>();
    __syncthreads();

    // ---- main loop: ch unrolled by 2 so buffer indices are literals ----
    auto body = [&](int ch, int cb) {
#pragma unroll
        for (int ds = 0; ds < 4; ds++) {
            float4 f0 = xr[cb][ds][0];
            float4 f1 = xr[cb][ds][1];
            ss0 += f0.x * f0.x + f0.y * f0.y + f0.z * f0.z + f0.w * f0.w;
            ss1 += f1.x * f1.x + f1.y * f1.y + f1.z * f1.z + f1.w * f1.w;
            unsigned a0 = packbf(f0.x, f0.y), a2 = packbf(f0.z, f0.w);
            unsigned a1 = packbf(f1.x, f1.y), a3 = packbf(f1.z, f1.w);
            {   // raw bf16 out (natural order) for k_vlad
                __nv_bfloat16* gx = g_x16 + row0 * ND + ch * 64 + ds * 16 + q * 4;
                uint2 u0; u0.x = a0; u0.y = a2;
                uint2 u1; u1.x = a1; u1.y = a3;
                *(uint2*)gx            = u0;
                *(uint2*)(gx + 8 * ND) = u1;
            }
#pragma unroll
            for (int nt = 0; nt < 8; nt += 2) {
                unsigned b0, b1, b2, b3;
                int r = nt * 8 + (lane & 7) + ((lane >> 4) & 1) * 8;
                int c = ds * 16 + ((lane >> 3) & 1) * 8;
                ldsm_x4(b0, b1, b2, b3, s2u(wt[cb] + r * 72 + c));
                mma16816(acc[nt],     a0, a1, a2, a3, b0, b1);
                mma16816(acc[nt + 1], a0, a1, a2, a3, b2, b3);
            }
        }
        if (ch + 2 < 16) {
#pragma unroll
            for (int ds = 0; ds < 4; ds++) {
                xr[cb][ds][0] = *(const float4*)(xb + (ch + 2) * 64 + ds * 16);
                xr[cb][ds][1] = *(const float4*)(xb + (ch + 2) * 64 + ds * 16 + 8 * ND);
            }
        }
        __syncthreads();                 // all reads of wt[cb] complete
        if (ch + 2 < 16) { ldw(ch + 2, cb); cp_wait<1>(); }
        else             cp_wait<0>();
        __syncthreads();                 // wt writes visible
    };
    for (int ch2 = 0; ch2 < 16; ch2 += 2) {
        body(ch2,     0);
        body(ch2 + 1, 1);
    }

    // ---- row sum-of-squares: reduce over the 4 q-lanes ----
    ss0 += __shfl_xor_sync(0xffffffffu, ss0, 1);
    ss0 += __shfl_xor_sync(0xffffffffu, ss0, 2);
    ss1 += __shfl_xor_sync(0xffffffffu, ss1, 1);
    ss1 += __shfl_xor_sync(0xffffffffu, ss1, 2);
    if (q == 0) {
        ssrow[ar + gr]     = ss0;
        ssrow[ar + gr + 8] = ss1;
    }
    // ---- dump logits ----
#pragma unroll
    for (int nt = 0; nt < 8; nt++) {
        int r0 = ar + (lane >> 2);
        int c0 = nt * 8 + 2 * (lane & 3);
        lg[r0 * 66 + c0]           = acc[nt][0];
        lg[r0 * 66 + c0 + 1]       = acc[nt][1];
        lg[(r0 + 8) * 66 + c0]     = acc[nt][2];
        lg[(r0 + 8) * 66 + c0 + 1] = acc[nt][3];
    }
    __syncthreads();

    // ---- softmax: each warp does its 16 rows; lane owns cols (2l, 2l+1) ----
    float s0 = 0.f, s1 = 0.f;
    const int c0 = 2 * lane, c1 = 2 * lane + 1;
#pragma unroll 1
    for (int r = 0; r < 16; r++) {
        int rr = ar + r;
        float inv = 1.0f / fmaxf(sqrtf(ssrow[rr]), 1e-12f);
        float v0 = lg[rr * 66 + c0] * inv, v1 = lg[rr * 66 + c1] * inv;
        float mx = fmaxf(v0, v1);
#pragma unroll
        for (int o = 16; o > 0; o >>= 1) mx = fmaxf(mx, __shfl_xor_sync(0xffffffffu, mx, o));
        float e0 = expf(v0 - mx), e1 = expf(v1 - mx);
        float sm = e0 + e1;
#pragma unroll
        for (int o = 16; o > 0; o >>= 1) sm += __shfl_xor_sync(0xffffffffu, sm, o);
        float is = 1.0f / sm;
        float p0 = e0 * is, p1 = e1 * is;
        s0 += p0; s1 += p1;
        __nv_bfloat162 h;                    // store p * inv_m  (normalization folded in)
        h.x = __float2bfloat16_rn(p0 * inv);
        h.y = __float2bfloat16_rn(p1 * inv);
        ((__nv_bfloat162*)(g_a + (size_t)(m0 + rr) * NK))[lane] = h;
    }
    atomicAdd(&sas[c0], s0);
    atomicAdd(&sas[c1], s1);
    __syncthreads();
    if (tid < 64) atomicAdd(&g_asum[b * NK + tid], sas[tid]);
    asm volatile("griddepcontrol.launch_dependents;");   // LATE trigger (R14-proven)
}

// ============ kernel: vlad + centroid-subtract + GLOBAL norm + final write ============
// (R11-proven body + PDL wait.) grid (8 d-tiles of 128, 32 b) = 256 CTAs, 2/SM ->
// <= 296 slots: guaranteed single co-resident wave, so the cross-CTA spin cannot
// deadlock. Full M=2048 per CTA (32 chunks), 2-stage cp.async double buffering.
// Epilogue: v = acc - asum*cent kept IN REGISTERS; deposit sumsq partial, spin
// until all 8 d-CTAs of this b arrive, read partials in fixed order
// (deterministic), scale regs by 0.125/||v||, write `out` directly.
//
// dyn smem: at[2] 9216 ea @0 | xt[2] 17408 ea @18432 | ssq_s[64] f32 @53248
#define VL_SMEM 53504
__global__ __launch_bounds__(256, 2) void k_vlad(const float* __restrict__ cent,
                                                 float* __restrict__ out) {
    extern __shared__ __align__(16) unsigned char dsm[];
    __nv_bfloat16* at[2] = { (__nv_bfloat16*)dsm,           (__nv_bfloat16*)(dsm + 9216) };
    __nv_bfloat16* xt[2] = { (__nv_bfloat16*)(dsm + 18432), (__nv_bfloat16*)(dsm + 35840) };
    float* ssq_s = (float*)(dsm + 53248);

    const int tid = threadIdx.x, lane = tid & 31, warp = tid >> 5;
    const int b  = blockIdx.y;
    const int d0 = blockIdx.x * 128;
    const int wk = (warp & 3) * 16;     // k-row base for this warp
    const int wd = (warp >> 2) * 64;    // d-col base within tile

    if (tid < 64) ssq_s[tid] = 0.f;

    const size_t rowbase = (size_t)b * NM;

    float acc[8][4];
#pragma unroll
    for (int i = 0; i < 8; i++)
#pragma unroll
        for (int j = 0; j < 4; j++) acc[i][j] = 0.f;

    auto issue = [&](int mc, int s) {
        const size_t mrow = rowbase + mc * 64;
#pragma unroll
        for (int it = 0; it < 2; it++) {     // a tile: 64 m x 64 k
            int idx = tid + it * 256;
            int r = idx >> 3, c = idx & 7;
            cp16(s2u(at[s] + r * 72 + c * 8), g_a + (mrow + r) * NK + c * 8);
        }
#pragma unroll
        for (int it = 0; it < 4; it++) {     // x tile: 64 m x 128 d
            int idx = tid + it * 256;
            int r = idx >> 4, c = idx & 15;
            cp16(s2u(xt[s] + r * 136 + c * 8), g_x16 + (mrow + r) * ND + d0 + c * 8);
        }
        cp_commit();
    };

    asm volatile("griddepcontrol.wait;" ::: "memory");   // k_nl outputs ready past here

    issue(0, 0);
    for (int mc = 0; mc < 32; mc++) {
        if (mc + 1 < 32) { issue(mc + 1, (mc + 1) & 1); cp_wait<1>(); }
        else             { cp_wait<0>(); }
        __syncthreads();
        const int s = mc & 1;
#pragma unroll
        for (int ms = 0; ms < 4; ms++) {
            int mb = ms * 16;
            unsigned a0, a1, a2, a3;
            {   // A = a^T (k x m) from [m][k] storage -> ldmatrix.trans
                int i = lane & 7;
                int r = mb + i + ((lane >> 4) & 1) * 8;
                int c = wk + ((lane >> 3) & 1) * 8;
                ldsm_x4t(a0, a1, a2, a3, s2u(at[s] + r * 72 + c));
            }
#pragma unroll
            for (int nt = 0; nt < 8; nt += 2) {
                unsigned b0, b1, b2, b3;
                int r = mb + (lane & 7) + ((lane >> 3) & 1) * 8;
                int c = wd + nt * 8 + ((lane >> 4) & 1) * 8;
                ldsm_x4t(b0, b1, b2, b3, s2u(xt[s] + r * 136 + c));
                mma16816(acc[nt],     a0, a1, a2, a3, b0, b1);
                mma16816(acc[nt + 1], a0, a1, a2, a3, b2, b3);
            }
        }
        __syncthreads();
    }

    // ---- epilogue part 1: v = acc - asum*cent (kept in regs), sumsq partials ----
    const int k0 = wk + (lane >> 2);
    const float as0 = g_asum[b * NK + k0];
    const float as1 = g_asum[b * NK + k0 + 8];
    float sq0 = 0.f, sq1 = 0.f;
#pragma unroll
    for (int nt = 0; nt < 8; nt++) {
        int dd = d0 + wd + nt * 8 + 2 * (lane & 3);
        float2 c0 = *(const float2*)(cent + (size_t)k0 * ND + dd);
        float2 c1 = *(const float2*)(cent + (size_t)(k0 + 8) * ND + dd);
        acc[nt][0] -= as0 * c0.x;
        acc[nt][1] -= as0 * c0.y;
        acc[nt][2] -= as1 * c1.x;
        acc[nt][3] -= as1 * c1.y;
        sq0 += acc[nt][0] * acc[nt][0] + acc[nt][1] * acc[nt][1];
        sq1 += acc[nt][2] * acc[nt][2] + acc[nt][3] * acc[nt][3];
    }
    // reduce over the 4 lanes sharing a k-row
    sq0 += __shfl_xor_sync(0xffffffffu, sq0, 1);
    sq0 += __shfl_xor_sync(0xffffffffu, sq0, 2);
    sq1 += __shfl_xor_sync(0xffffffffu, sq1, 1);
    sq1 += __shfl_xor_sync(0xffffffffu, sq1, 2);
    if ((lane & 3) == 0) {        // 2 warps (wd halves) contribute per row slot
        atomicAdd(&ssq_s[k0], sq0);
        atomicAdd(&ssq_s[k0 + 8], sq1);
    }
    __syncthreads();
    if (tid < 64)
        g_ssq[(b * NK + tid) * 8 + blockIdx.x] = ssq_s[tid];
    __threadfence();              // make this CTA's partial globally visible
    __syncthreads();

    // ---- epilogue part 2: arrive + spin until all 8 d-CTAs of this b done ----
    if (tid == 0) {
        atomicAdd(&g_cnt[b], 1);
        int v;
        do {
            asm volatile("ld.global.acquire.gpu.s32 %0, [%1];" : "=r"(v) : "l"(g_cnt + b));
        } while (v < 8);
    }
    __syncthreads();

    // ---- epilogue part 3: global tot (fixed order), scale regs, write out ----
    float tot0 = 0.f, tot1 = 0.f;
#pragma unroll
    for (int j = 0; j < 8; j++) {
        tot0 += __ldcg(g_ssq + (b * NK + k0) * 8 + j);
        tot1 += __ldcg(g_ssq + (b * NK + k0 + 8) * 8 + j);
    }
    const float inv0 = 0.125f / fmaxf(sqrtf(tot0), 1e-12f);   // global norm = 8 exactly
    const float inv1 = 0.125f / fmaxf(sqrtf(tot1), 1e-12f);
    float* ob = out + ((size_t)b * NK) * ND;
#pragma unroll
    for (int nt = 0; nt < 8; nt++) {
        int dd = d0 + wd + nt * 8 + 2 * (lane & 3);
        *(float2*)(ob + (size_t)k0 * ND + dd) =
            make_float2(acc[nt][0] * inv0, acc[nt][1] * inv0);
        *(float2*)(ob + (size_t)(k0 + 8) * ND + dd) =
            make_float2(acc[nt][2] * inv1, acc[nt][3] * inv1);
    }
}

// ---------------- launch (PDL-chained; k_final folded into k_vlad) ----------------
extern "C" void kernel_launch(void* const* d_in, const int* in_sizes, int n_in,
                              void* d_out, int out_size) {
    const float* x    = (const float*)d_in[0];
    const float* W    = (const float*)d_in[1];
    const float* cent = (const float*)d_in[2];
    float* out = (float*)d_out;

    static int configured = 0;
    if (!configured) {
        cudaFuncSetAttribute(k_nl,   cudaFuncAttributeMaxDynamicSharedMemorySize, NL_SMEM);
        cudaFuncSetAttribute(k_vlad, cudaFuncAttributeMaxDynamicSharedMemorySize, VL_SMEM);
        configured = 1;
    }

    k_wconv<<<256, 256>>>(W);

    cudaLaunchAttribute pdl[1];
    pdl[0].id = cudaLaunchAttributeProgrammaticStreamSerialization;
    pdl[0].val.programmaticStreamSerializationAllowed = 1;

    {
        cudaLaunchConfig_t cfg{};
        cfg.gridDim = dim3(512, 1, 1);
        cfg.blockDim = dim3(256, 1, 1);
        cfg.dynamicSmemBytes = NL_SMEM;
        cfg.stream = 0;
        cfg.attrs = pdl;
        cfg.numAttrs = 1;
        cudaLaunchKernelEx(&cfg, k_nl, x);
    }
    {
        cudaLaunchConfig_t cfg{};
        cfg.gridDim = dim3(8, 32, 1);
        cfg.blockDim = dim3(256, 1, 1);
        cfg.dynamicSmemBytes = VL_SMEM;
        cfg.stream = 0;
        cfg.attrs = pdl;
        cfg.numAttrs = 1;
        cudaLaunchKernelEx(&cfg, k_vlad, cent, out);
    }
}